// round 16
// baseline (speedup 1.0000x reference)
#include <cuda_runtime.h>
#include <cuda_fp16.h>
#include <math.h>
#include <cstdint>

#define B 8
#define C 128
#define L 41

// ---- scratch (static device globals; no allocations) ----
__device__ __half g_fuse[(size_t)B*C*128*128];     // 32 MB conv output (fp16, fp32-accumulated)
__device__ __half g_vin[(size_t)B*128*128*256];    // 64 MB, [b][row][col][civ] half
__device__ __half g_wH[144*128*16];                // [cc*9+tap][co 128][k 16] half
__device__ float  g_sums[2*B*L*C];
__device__ int    g_cnt[B*L];
__device__ float  g_gates[2*B*C];

// ============================================================================
// helpers
// ============================================================================
__device__ __forceinline__ void mma_f16(float* c,
        uint32_t a0, uint32_t a1, uint32_t a2, uint32_t a3,
        uint32_t b0, uint32_t b1){
    asm volatile("mma.sync.aligned.m16n8k16.row.col.f32.f16.f16.f32 "
                 "{%0,%1,%2,%3},{%4,%5,%6,%7},{%8,%9},{%0,%1,%2,%3};"
                 : "+f"(c[0]), "+f"(c[1]), "+f"(c[2]), "+f"(c[3])
                 : "r"(a0), "r"(a1), "r"(a2), "r"(a3), "r"(b0), "r"(b1));
}
__device__ __forceinline__ void ldsm_x4(uint32_t& r0, uint32_t& r1,
                                        uint32_t& r2, uint32_t& r3, uint32_t addr){
    asm volatile("ldmatrix.sync.aligned.m8n8.x4.shared.b16 {%0,%1,%2,%3}, [%4];"
                 : "=r"(r0), "=r"(r1), "=r"(r2), "=r"(r3) : "r"(addr));
}
__device__ __forceinline__ void cp16(uint32_t dst, const void* src, int sz){
    asm volatile("cp.async.cg.shared.global [%0], [%1], 16, %2;"
                 :: "r"(dst), "l"(src), "r"(sz));
}
#define CP_COMMIT() asm volatile("cp.async.commit_group;" ::: "memory")
#define CP_WAIT1()  asm volatile("cp.async.wait_group 1;" ::: "memory")
#define CP_WAIT0()  asm volatile("cp.async.wait_group 0;" ::: "memory")
__device__ __forceinline__ uint32_t h2_u32(__half2 h){
    return *(uint32_t*)&h;
}

// ============================================================================
// Virtual input prep, channel-contiguous transposed layout:
//   g_vin[b][row][col][ch]     = half(r+d)            ch in [0,128)
//   g_vin[b][row][col][128+ch] = half(r*sigmoid(d))
// ============================================================================
__global__ void __launch_bounds__(256) vin_prep(const float* __restrict__ r,
                                                const float* __restrict__ d)
{
    const int row = blockIdx.x, b = blockIdx.y;
    const int t = threadIdx.x;
    const int cp = t & 63, seg = t >> 6;
    const size_t in0 = (((size_t)b*128 + 2*cp)*128 + row)*128 + seg*32;
    const float4* R0 = (const float4*)(r + in0);
    const float4* R1 = (const float4*)(r + in0 + 16384);
    const float4* D0 = (const float4*)(d + in0);
    const float4* D1 = (const float4*)(d + in0 + 16384);
    __half* vout = g_vin + (((size_t)b*128 + row)*128)*256;

    #pragma unroll
    for (int i4 = 0; i4 < 8; i4++) {
        float4 ra = R0[i4], rb = R1[i4];
        float4 da = D0[i4], db = D1[i4];
        float av0[4] = {ra.x+da.x, ra.y+da.y, ra.z+da.z, ra.w+da.w};
        float av1[4] = {rb.x+db.x, rb.y+db.y, rb.z+db.z, rb.w+db.w};
        float mv0[4] = {ra.x/(1.f+__expf(-da.x)), ra.y/(1.f+__expf(-da.y)),
                        ra.z/(1.f+__expf(-da.z)), ra.w/(1.f+__expf(-da.w))};
        float mv1[4] = {rb.x/(1.f+__expf(-db.x)), rb.y/(1.f+__expf(-db.y)),
                        rb.z/(1.f+__expf(-db.z)), rb.w/(1.f+__expf(-db.w))};
        #pragma unroll
        for (int u = 0; u < 4; u++) {
            int col = seg*32 + i4*4 + u;
            *(__half2*)(vout + (size_t)col*256 + 2*cp)       = __floats2half2_rn(av0[u], av1[u]);
            *(__half2*)(vout + (size_t)col*256 + 128 + 2*cp) = __floats2half2_rn(mv0[u], mv1[u]);
        }
    }
}

// ============================================================================
// Weight pre-transform: cw[co][civ][tap] -> g_wH[(cc*9+tap)][co][k16] half
// ============================================================================
__global__ void __launch_bounds__(256) wpre_kernel(const float* __restrict__ cw)
{
    int tile = blockIdx.x;               // 0..143
    int cc = tile / 9, tap = tile % 9;
    for (int i = threadIdx.x; i < 2048; i += 256) {
        int co = i >> 4, kk = i & 15;
        float v = cw[(co*256 + cc*16 + kk)*9 + tap];
        g_wH[tile*2048 + co*16 + kk] = __float2half_rn(v);
    }
}

// ============================================================================
// Conv3x3 via mma.sync fp16 m16n8k16 implicit GEMM + ldmatrix + cp.async
// double-buffered K-pipeline (16 chunks of 16 channels).  (R14 exact.)
// CTA = (rowpair, cog, b): 64 co x 2 rows x 128 px. 8 warps, warp 32co x 64px.
// XOR-swizzled 32B smem rows; buffers 69 KB -> 2 CTAs/SM.
// ============================================================================
#define SBB 16896                 // bytes per B buffer (528 rows x 32B)
#define SAB 18432                 // bytes per A buffer (576 rows x 32B)
#define CONV_SMEM (2*SBB + 2*SAB) // 70656

__global__ void __launch_bounds__(256, 2) conv_mma(const __half* __restrict__ vin,
                                                   const __half* __restrict__ wH)
{
    extern __shared__ __half sm[];
    const uint32_t sb_u = (uint32_t)__cvta_generic_to_shared(sm);

    const int t = threadIdx.x, w = t >> 5, lane = t & 31;
    const int gid = lane >> 2, tid4 = lane & 3;
    const int rp = blockIdx.x, cog = blockIdx.y, b = blockIdx.z;
    const int h0 = rp * 2;
    const int wm = w & 1, wq = w >> 1;
    const int rl = wq >> 1, pxb = (wq & 1) * 64;

    // ldmatrix lane->row maps
    const int arow = lane & 15;                          // A: row within m16
    const int kgA  = (lane >> 4) & 1;                    // A: k half 0/1
    const int brow = (lane & 7) + ((lane & 16) ? 8 : 0); // B: px row within n16
    const int kgB  = (lane >> 3) & 1;                    // B: k half 0/1
    const uint32_t aswz = (uint32_t)((kgA ^ ((arow >> 2) & 1)) << 4);

    float acc[2][8][4];
    #pragma unroll
    for (int i = 0; i < 2; i++)
        #pragma unroll
        for (int j = 0; j < 8; j++)
            #pragma unroll
            for (int q = 0; q < 4; q++) acc[i][j][q] = 0.f;

    const __half* vb = vin + (size_t)b * 128 * 128 * 256;

    // ---- staging: issue cp.async for chunk cc into buffer cc&1 ----
    auto stage = [&](int cc) {
        const uint32_t bufB = sb_u + (cc & 1) * SBB;
        const uint32_t bufA = sb_u + 2*SBB + (cc & 1) * SAB;
        // B: 4 rows x 132 px x 2 k-halves = 1056 x 16B
        #pragma unroll
        for (int it = 0; it < 5; it++) {
            int i = t + it*256;
            if (i < 1056) {
                int j = i / 264;
                int rm = i - j*264;
                int px = rm >> 1, kg = rm & 1;
                int rho = j*132 + px;
                uint32_t dst = bufB + rho*32 + ((kg ^ ((rho >> 2) & 1)) << 4);
                int row = h0 - 1 + j, col = px - 1;
                bool ok = (unsigned)row < 128u && (unsigned)col < 128u;
                const __half* src = ok ? vb + ((size_t)row*128 + col)*256 + cc*16 + kg*8
                                       : vb;
                cp16(dst, src, ok ? 16 : 0);
            }
        }
        // A: 9 taps x 64 co x 2 k-halves = 1152 x 16B
        #pragma unroll
        for (int it = 0; it < 5; it++) {
            int i = t + it*256;
            if (i < 1152) {
                int tap = i >> 7;
                int rm = i & 127;
                int co = rm >> 1, kg = rm & 1;
                int rhoA = tap*64 + co;
                uint32_t dst = bufA + rhoA*32 + ((kg ^ ((rhoA >> 2) & 1)) << 4);
                const __half* src = wH + ((size_t)(cc*9 + tap)*128 + cog*64 + co)*16 + kg*8;
                cp16(dst, src, 16);
            }
        }
    };

    stage(0); CP_COMMIT();

    for (int cc = 0; cc < 16; cc++) {
        if (cc < 15) { stage(cc + 1); CP_COMMIT(); CP_WAIT1(); }
        else         { CP_WAIT0(); }
        __syncthreads();

        const uint32_t bufB = sb_u + (cc & 1) * SBB;
        const uint32_t bufA = sb_u + 2*SBB + (cc & 1) * SAB;

        #pragma unroll
        for (int tap = 0; tap < 9; tap++) {
            const int ky = tap / 3, dx = tap % 3;
            uint32_t a0[4], a1[4];
            ldsm_x4(a0[0], a0[1], a0[2], a0[3],
                    bufA + (uint32_t)(tap*64 + wm*32 + arow)*32 + aswz);
            ldsm_x4(a1[0], a1[1], a1[2], a1[3],
                    bufA + (uint32_t)(tap*64 + wm*32 + 16 + arow)*32 + aswz);

            const int rowbase = (rl + ky)*132 + dx + pxb + brow;
            const uint32_t baddr = bufB + (uint32_t)rowbase*32
                                 + (uint32_t)((kgB ^ ((rowbase >> 2) & 1)) << 4);
            #pragma unroll
            for (int q = 0; q < 4; q++) {
                uint32_t bb[4];
                ldsm_x4(bb[0], bb[1], bb[2], bb[3], baddr + q*512);
                mma_f16(acc[0][2*q],   a0[0], a0[1], a0[2], a0[3], bb[0], bb[1]);
                mma_f16(acc[1][2*q],   a1[0], a1[1], a1[2], a1[3], bb[0], bb[1]);
                mma_f16(acc[0][2*q+1], a0[0], a0[1], a0[2], a0[3], bb[2], bb[3]);
                mma_f16(acc[1][2*q+1], a1[0], a1[1], a1[2], a1[3], bb[2], bb[3]);
            }
        }
        __syncthreads();
    }

    // ---- epilogue: fp32 acc -> half2 stores ----
    const int h = h0 + rl;
    #pragma unroll
    for (int mt = 0; mt < 2; mt++) {
        int co = cog*64 + wm*32 + mt*16 + gid;
        size_t base = (((size_t)b*128 + co)*128 + h)*128 + pxb + 2*tid4;
        #pragma unroll
        for (int nt = 0; nt < 8; nt++) {
            *(__half2*)&g_fuse[base + nt*8] =
                __floats2half2_rn(acc[mt][nt][0], acc[mt][nt][1]);
            *(__half2*)&g_fuse[base + (size_t)8*16384 + nt*8] =
                __floats2half2_rn(acc[mt][nt][2], acc[mt][nt][3]);
        }
    }
}

// ============================================================================
__global__ void zero_kernel()
{
    int i = blockIdx.x * blockDim.x + threadIdx.x;
    if (i < 2*B*L*C) g_sums[i] = 0.f;
}

// ============================================================================
__global__ void __launch_bounds__(256) hist_kernel(const int* __restrict__ label)
{
    __shared__ int hc[L];
    int t = threadIdx.x, b = blockIdx.x;
    if (t < L) hc[t] = 0;
    __syncthreads();
    for (int p = t; p < 16384; p += 256) {
        int lb = label[(b*512 + ((p >> 7) << 2))*512 + ((p & 127) << 2)];
        atomicAdd(&hc[lb], 1);
    }
    __syncthreads();
    if (t < L) g_cnt[b*L + t] = hc[t];
}

// ============================================================================
// Segment sums as one-hot GEMM (fp16 m16n8k16), smem-free.
// set=0: A from d (fp32 -> cvt). set=1: A direct u32 loads from half g_fuse.
// ============================================================================
__global__ void __launch_bounds__(256) stats_mma(const float* __restrict__ dd,
                                                 const int*   __restrict__ label,
                                                 int set)
{
    const int t = threadIdx.x, w = t >> 5, lane = t & 31;
    const int gid = lane >> 2, tid4 = lane & 3;
    const int kc = blockIdx.x, b = blockIdx.y;
    const float* Xf = dd + (size_t)b * 128 * 16384;
    const __half* Xh = g_fuse + (size_t)b * 128 * 16384;
    const int c0 = w * 16;

    float acc[6][4];
    #pragma unroll
    for (int i = 0; i < 6; i++)
        #pragma unroll
        for (int q = 0; q < 4; q++) acc[i][q] = 0.f;

    for (int chunk = 0; chunk < 32; chunk++) {
        const int p0 = kc*1024 + chunk*32;
        const int p = p0 + lane;
        const int ll = label[(b*512 + ((p >> 7) << 2))*512 + ((p & 127) << 2)];

        #pragma unroll
        for (int ks = 0; ks < 2; ks++) {
            const int koff = ks*16 + 2*tid4;
            uint32_t a0, a1, a2, a3;
            if (set == 0) {
                const float* xr = Xf + (size_t)(c0 + gid)*16384 + p0 + koff;
                float2 f0 = *(const float2*)(xr);
                float2 f1 = *(const float2*)(xr + (size_t)8*16384);
                float2 f2 = *(const float2*)(xr + 8);
                float2 f3 = *(const float2*)(xr + (size_t)8*16384 + 8);
                a0 = h2_u32(__floats2half2_rn(f0.x, f0.y));
                a1 = h2_u32(__floats2half2_rn(f1.x, f1.y));
                a2 = h2_u32(__floats2half2_rn(f2.x, f2.y));
                a3 = h2_u32(__floats2half2_rn(f3.x, f3.y));
            } else {
                const __half* xr = Xh + (size_t)(c0 + gid)*16384 + p0 + koff;
                a0 = *(const uint32_t*)(xr);
                a1 = *(const uint32_t*)(xr + (size_t)8*16384);
                a2 = *(const uint32_t*)(xr + 8);
                a3 = *(const uint32_t*)(xr + (size_t)8*16384 + 8);
            }

            int l0 = __shfl_sync(0xffffffffu, ll, koff);
            int l1 = __shfl_sync(0xffffffffu, ll, koff + 1);
            int l2 = __shfl_sync(0xffffffffu, ll, koff + 8);
            int l3 = __shfl_sync(0xffffffffu, ll, koff + 9);

            #pragma unroll
            for (int nt = 0; nt < 6; nt++) {
                int cls = nt*8 + gid;
                uint32_t b0 = ((l0 == cls) ? 0x3C00u : 0u) | ((l1 == cls) ? 0x3C000000u : 0u);
                uint32_t b1 = ((l2 == cls) ? 0x3C00u : 0u) | ((l3 == cls) ? 0x3C000000u : 0u);
                mma_f16(acc[nt], a0, a1, a2, a3, b0, b1);
            }
        }
    }

    float* gs = g_sums + (size_t)(set*B + b) * L * C;
    int c = c0 + gid;
    #pragma unroll
    for (int nt = 0; nt < 6; nt++) {
        int l0 = nt*8 + 2*tid4;
        if (l0 < L)     atomicAdd(&gs[l0*128 + c],        acc[nt][0]);
        if (l0 + 1 < L) atomicAdd(&gs[(l0+1)*128 + c],    acc[nt][1]);
        if (l0 < L)     atomicAdd(&gs[l0*128 + c + 8],    acc[nt][2]);
        if (l0 + 1 < L) atomicAdd(&gs[(l0+1)*128 + c + 8], acc[nt][3]);
    }
}

// ============================================================================
__global__ void __launch_bounds__(128) gate_kernel(const float* __restrict__ fw1,
                                                   const float* __restrict__ fw2,
                                                   const float* __restrict__ dw1,
                                                   const float* __restrict__ dw2,
                                                   const float* __restrict__ basef,
                                                   const float* __restrict__ based)
{
    __shared__ float ss[128];
    __shared__ float sh[8];
    const int c = threadIdx.x;
    const int b = blockIdx.x, set = blockIdx.y;
    const float* sums = g_sums + (set*B + b)*L*C;
    const float* base = ((set == 0) ? based : basef) + b*L*C;
    const int*   cnt  = g_cnt + b*L;

    float suml = 0.f, sq = 0.f;
    for (int l = 0; l < L; l++) {
        int n = cnt[l];
        float m = (n > 0) ? sums[l*128 + c] / (float)n : base[l*128 + c];
        suml += m; sq += m*m;
    }
    ss[c] = suml / fmaxf(sqrtf(sq), 1e-12f);
    __syncthreads();

    if (c < 8) {
        const float* w1 = ((set == 0) ? dw1 : fw1) + c*128;
        float hsum = 0.f;
        for (int k = 0; k < 128; k++) hsum += ss[k] * w1[k];
        sh[c] = fmaxf(hsum, 0.f);
    }
    __syncthreads();

    const float* w2 = ((set == 0) ? dw2 : fw2) + c*8;
    float g = 0.f;
    #pragma unroll
    for (int o = 0; o < 8; o++) g += sh[o] * w2[o];
    g_gates[(set*B + b)*C + c] = 1.f / (1.f + expf(-g));
}

// ============================================================================
// out = fuse(half) * gate_f[b,c] + d * gate_d[b,c]
// ============================================================================
__global__ void __launch_bounds__(256) out_kernel(const float* __restrict__ dd,
                                                  float* __restrict__ out)
{
    int idx = blockIdx.x * blockDim.x + threadIdx.x;   // float4 index
    int bc = idx >> 12;
    int b = bc >> 7, c = bc & 127;
    float gf = g_gates[(B + b)*C + c];
    float gd = g_gates[b*C + c];
    uint2 fh = ((const uint2*)g_fuse)[idx];
    float2 fa = __half22float2(*(__half2*)&fh.x);
    float2 fb = __half22float2(*(__half2*)&fh.y);
    float4 d4 = ((const float4*)dd)[idx];
    float4 o;
    o.x = fa.x*gf + d4.x*gd;
    o.y = fa.y*gf + d4.y*gd;
    o.z = fb.x*gf + d4.z*gd;
    o.w = fb.y*gf + d4.w*gd;
    ((float4*)out)[idx] = o;
}

// ============================================================================
extern "C" void kernel_launch(void* const* d_in, const int* in_sizes, int n_in,
                              void* d_out, int out_size)
{
    const float* r   = (const float*)d_in[0];
    const float* d   = (const float*)d_in[1];
    const int*   lab = (const int*)  d_in[2];
    const float* cw  = (const float*)d_in[3];
    const float* fw1 = (const float*)d_in[4];
    const float* fw2 = (const float*)d_in[5];
    const float* dw1 = (const float*)d_in[6];
    const float* dw2 = (const float*)d_in[7];
    const float* bf  = (const float*)d_in[8];
    const float* bd  = (const float*)d_in[9];
    float* out = (float*)d_out;

    static cudaStream_t s2 = nullptr;
    static cudaEvent_t eFork = nullptr, eJoin = nullptr;
    if (!s2) {
        cudaStreamCreateWithFlags(&s2, cudaStreamNonBlocking);
        cudaEventCreateWithFlags(&eFork, cudaEventDisableTiming);
        cudaEventCreateWithFlags(&eJoin, cudaEventDisableTiming);
        cudaFuncSetAttribute(conv_mma, cudaFuncAttributeMaxDynamicSharedMemorySize, CONV_SMEM);
    }

    __half* vin_ptr = nullptr;
    __half* wH_ptr = nullptr;
    cudaGetSymbolAddress((void**)&vin_ptr, g_vin);
    cudaGetSymbolAddress((void**)&wH_ptr,  g_wH);

    // ---- main chain: prep (memory-bound) runs alone, then conv (tensor-bound) ----
    wpre_kernel<<<144, 256>>>(cw);
    vin_prep<<<dim3(128, 8), 256>>>(r, d);

    // ---- fork AFTER vin_prep: DRAM-bound side work overlaps the tensor-bound conv ----
    cudaEventRecord(eFork, 0);
    cudaStreamWaitEvent(s2, eFork, 0);
    zero_kernel<<<328, 256, 0, s2>>>();
    hist_kernel<<<8, 256, 0, s2>>>(lab);
    stats_mma<<<dim3(16, 8), 256, 0, s2>>>(d, lab, 0);
    cudaEventRecord(eJoin, s2);

    conv_mma<<<dim3(64, 2, 8), 256, CONV_SMEM>>>(vin_ptr, wH_ptr);
    cudaStreamWaitEvent(0, eJoin, 0);                 // join: zero/hist/stats_d done
    stats_mma<<<dim3(16, 8), 256>>>(d, lab, 1);       // fuse-set stats
    gate_kernel<<<dim3(8, 2), 128>>>(fw1, fw2, dw1, dw2, bf, bd);
    out_kernel<<<16384, 256>>>(d, out);
}

// round 17
// speedup vs baseline: 1.0602x; 1.0602x over previous
#include <cuda_runtime.h>
#include <cuda_fp16.h>
#include <math.h>
#include <cstdint>

#define B 8
#define C 128
#define L 41

// ---- scratch (static device globals; no allocations) ----
__device__ __half g_fuse[(size_t)B*C*128*128];     // 32 MB conv output (fp16, fp32-accumulated)
__device__ __half g_vin[(size_t)B*128*128*256];    // 64 MB, [b][row][col][civ] half
__device__ __half g_wH[144*128*16];                // [cc*9+tap][co 128][k 16] half
__device__ float  g_sums[2*B*L*C];
__device__ int    g_cnt[B*L];
__device__ float  g_gates[2*B*C];

// ============================================================================
// helpers
// ============================================================================
__device__ __forceinline__ void mma_f16(float* c,
        uint32_t a0, uint32_t a1, uint32_t a2, uint32_t a3,
        uint32_t b0, uint32_t b1){
    asm volatile("mma.sync.aligned.m16n8k16.row.col.f32.f16.f16.f32 "
                 "{%0,%1,%2,%3},{%4,%5,%6,%7},{%8,%9},{%0,%1,%2,%3};"
                 : "+f"(c[0]), "+f"(c[1]), "+f"(c[2]), "+f"(c[3])
                 : "r"(a0), "r"(a1), "r"(a2), "r"(a3), "r"(b0), "r"(b1));
}
__device__ __forceinline__ void ldsm_x4(uint32_t& r0, uint32_t& r1,
                                        uint32_t& r2, uint32_t& r3, uint32_t addr){
    asm volatile("ldmatrix.sync.aligned.m8n8.x4.shared.b16 {%0,%1,%2,%3}, [%4];"
                 : "=r"(r0), "=r"(r1), "=r"(r2), "=r"(r3) : "r"(addr));
}
__device__ __forceinline__ void cp16(uint32_t dst, const void* src, int sz){
    asm volatile("cp.async.cg.shared.global [%0], [%1], 16, %2;"
                 :: "r"(dst), "l"(src), "r"(sz));
}
#define CP_COMMIT() asm volatile("cp.async.commit_group;" ::: "memory")
#define CP_WAIT1()  asm volatile("cp.async.wait_group 1;" ::: "memory")
#define CP_WAIT0()  asm volatile("cp.async.wait_group 0;" ::: "memory")
__device__ __forceinline__ uint32_t h2_u32(__half2 h){
    return *(uint32_t*)&h;
}

// ============================================================================
// Fused prep: blocks [0,1024) do vin transform; blocks [1024,1168) do wpre.
//   g_vin[b][row][col][ch]     = half(r+d)            ch in [0,128)
//   g_vin[b][row][col][128+ch] = half(r*sigmoid(d))
//   g_wH[(cc*9+tap)][co][k16]  = half(cw[co][cc*16+k][tap])
// ============================================================================
__global__ void __launch_bounds__(256) prep_kernel(const float* __restrict__ r,
                                                   const float* __restrict__ d,
                                                   const float* __restrict__ cw)
{
    const int t = threadIdx.x;
    if (blockIdx.x >= 1024) {
        // ---- wpre role ----
        int tile = blockIdx.x - 1024;        // 0..143
        int cc = tile / 9, tap = tile % 9;
        float v[8];
        #pragma unroll
        for (int it = 0; it < 8; it++) {
            int i = t + it*256;
            int co = i >> 4, kk = i & 15;
            v[it] = cw[(co*256 + cc*16 + kk)*9 + tap];
        }
        #pragma unroll
        for (int it = 0; it < 8; it++) {
            int i = t + it*256;
            g_wH[tile*2048 + i] = __float2half_rn(v[it]);
        }
        return;
    }

    // ---- vin role ----
    const int row = blockIdx.x & 127, b = blockIdx.x >> 7;
    const int cp = t & 63, seg = t >> 6;
    const size_t in0 = (((size_t)b*128 + 2*cp)*128 + row)*128 + seg*32;
    const float4* R0 = (const float4*)(r + in0);
    const float4* R1 = (const float4*)(r + in0 + 16384);
    const float4* D0 = (const float4*)(d + in0);
    const float4* D1 = (const float4*)(d + in0 + 16384);
    __half* vout = g_vin + (((size_t)b*128 + row)*128)*256;

    #pragma unroll
    for (int i4 = 0; i4 < 8; i4++) {
        float4 ra = R0[i4], rb = R1[i4];
        float4 da = D0[i4], db = D1[i4];
        float av0[4] = {ra.x+da.x, ra.y+da.y, ra.z+da.z, ra.w+da.w};
        float av1[4] = {rb.x+db.x, rb.y+db.y, rb.z+db.z, rb.w+db.w};
        float mv0[4] = {ra.x/(1.f+__expf(-da.x)), ra.y/(1.f+__expf(-da.y)),
                        ra.z/(1.f+__expf(-da.z)), ra.w/(1.f+__expf(-da.w))};
        float mv1[4] = {rb.x/(1.f+__expf(-db.x)), rb.y/(1.f+__expf(-db.y)),
                        rb.z/(1.f+__expf(-db.z)), rb.w/(1.f+__expf(-db.w))};
        #pragma unroll
        for (int u = 0; u < 4; u++) {
            int col = seg*32 + i4*4 + u;
            *(__half2*)(vout + (size_t)col*256 + 2*cp)       = __floats2half2_rn(av0[u], av1[u]);
            *(__half2*)(vout + (size_t)col*256 + 128 + 2*cp) = __floats2half2_rn(mv0[u], mv1[u]);
        }
    }
}

// ============================================================================
// Conv3x3 via mma.sync fp16 m16n8k16 implicit GEMM + ldmatrix + cp.async
// double-buffered K-pipeline (16 chunks of 16 channels).  (R14 exact.)
// CTA = (rowpair, cog, b): 64 co x 2 rows x 128 px. 8 warps, warp 32co x 64px.
// XOR-swizzled 32B smem rows; buffers 69 KB -> 2 CTAs/SM.
// ============================================================================
#define SBB 16896                 // bytes per B buffer (528 rows x 32B)
#define SAB 18432                 // bytes per A buffer (576 rows x 32B)
#define CONV_SMEM (2*SBB + 2*SAB) // 70656

__global__ void __launch_bounds__(256, 2) conv_mma(const __half* __restrict__ vin,
                                                   const __half* __restrict__ wH)
{
    extern __shared__ __half sm[];
    const uint32_t sb_u = (uint32_t)__cvta_generic_to_shared(sm);

    const int t = threadIdx.x, w = t >> 5, lane = t & 31;
    const int gid = lane >> 2, tid4 = lane & 3;
    const int rp = blockIdx.x, cog = blockIdx.y, b = blockIdx.z;
    const int h0 = rp * 2;
    const int wm = w & 1, wq = w >> 1;
    const int rl = wq >> 1, pxb = (wq & 1) * 64;

    // ldmatrix lane->row maps
    const int arow = lane & 15;                          // A: row within m16
    const int kgA  = (lane >> 4) & 1;                    // A: k half 0/1
    const int brow = (lane & 7) + ((lane & 16) ? 8 : 0); // B: px row within n16
    const int kgB  = (lane >> 3) & 1;                    // B: k half 0/1
    const uint32_t aswz = (uint32_t)((kgA ^ ((arow >> 2) & 1)) << 4);

    float acc[2][8][4];
    #pragma unroll
    for (int i = 0; i < 2; i++)
        #pragma unroll
        for (int j = 0; j < 8; j++)
            #pragma unroll
            for (int q = 0; q < 4; q++) acc[i][j][q] = 0.f;

    const __half* vb = vin + (size_t)b * 128 * 128 * 256;

    // ---- staging: issue cp.async for chunk cc into buffer cc&1 ----
    auto stage = [&](int cc) {
        const uint32_t bufB = sb_u + (cc & 1) * SBB;
        const uint32_t bufA = sb_u + 2*SBB + (cc & 1) * SAB;
        // B: 4 rows x 132 px x 2 k-halves = 1056 x 16B
        #pragma unroll
        for (int it = 0; it < 5; it++) {
            int i = t + it*256;
            if (i < 1056) {
                int j = i / 264;
                int rm = i - j*264;
                int px = rm >> 1, kg = rm & 1;
                int rho = j*132 + px;
                uint32_t dst = bufB + rho*32 + ((kg ^ ((rho >> 2) & 1)) << 4);
                int row = h0 - 1 + j, col = px - 1;
                bool ok = (unsigned)row < 128u && (unsigned)col < 128u;
                const __half* src = ok ? vb + ((size_t)row*128 + col)*256 + cc*16 + kg*8
                                       : vb;
                cp16(dst, src, ok ? 16 : 0);
            }
        }
        // A: 9 taps x 64 co x 2 k-halves = 1152 x 16B
        #pragma unroll
        for (int it = 0; it < 5; it++) {
            int i = t + it*256;
            if (i < 1152) {
                int tap = i >> 7;
                int rm = i & 127;
                int co = rm >> 1, kg = rm & 1;
                int rhoA = tap*64 + co;
                uint32_t dst = bufA + rhoA*32 + ((kg ^ ((rhoA >> 2) & 1)) << 4);
                const __half* src = wH + ((size_t)(cc*9 + tap)*128 + cog*64 + co)*16 + kg*8;
                cp16(dst, src, 16);
            }
        }
    };

    stage(0); CP_COMMIT();

    for (int cc = 0; cc < 16; cc++) {
        if (cc < 15) { stage(cc + 1); CP_COMMIT(); CP_WAIT1(); }
        else         { CP_WAIT0(); }
        __syncthreads();

        const uint32_t bufB = sb_u + (cc & 1) * SBB;
        const uint32_t bufA = sb_u + 2*SBB + (cc & 1) * SAB;

        #pragma unroll
        for (int tap = 0; tap < 9; tap++) {
            const int ky = tap / 3, dx = tap % 3;
            uint32_t a0[4], a1[4];
            ldsm_x4(a0[0], a0[1], a0[2], a0[3],
                    bufA + (uint32_t)(tap*64 + wm*32 + arow)*32 + aswz);
            ldsm_x4(a1[0], a1[1], a1[2], a1[3],
                    bufA + (uint32_t)(tap*64 + wm*32 + 16 + arow)*32 + aswz);

            const int rowbase = (rl + ky)*132 + dx + pxb + brow;
            const uint32_t baddr = bufB + (uint32_t)rowbase*32
                                 + (uint32_t)((kgB ^ ((rowbase >> 2) & 1)) << 4);
            #pragma unroll
            for (int q = 0; q < 4; q++) {
                uint32_t bb[4];
                ldsm_x4(bb[0], bb[1], bb[2], bb[3], baddr + q*512);
                mma_f16(acc[0][2*q],   a0[0], a0[1], a0[2], a0[3], bb[0], bb[1]);
                mma_f16(acc[1][2*q],   a1[0], a1[1], a1[2], a1[3], bb[0], bb[1]);
                mma_f16(acc[0][2*q+1], a0[0], a0[1], a0[2], a0[3], bb[2], bb[3]);
                mma_f16(acc[1][2*q+1], a1[0], a1[1], a1[2], a1[3], bb[2], bb[3]);
            }
        }
        __syncthreads();
    }

    // ---- epilogue: fp32 acc -> half2 stores ----
    const int h = h0 + rl;
    #pragma unroll
    for (int mt = 0; mt < 2; mt++) {
        int co = cog*64 + wm*32 + mt*16 + gid;
        size_t base = (((size_t)b*128 + co)*128 + h)*128 + pxb + 2*tid4;
        #pragma unroll
        for (int nt = 0; nt < 8; nt++) {
            *(__half2*)&g_fuse[base + nt*8] =
                __floats2half2_rn(acc[mt][nt][0], acc[mt][nt][1]);
            *(__half2*)&g_fuse[base + (size_t)8*16384 + nt*8] =
                __floats2half2_rn(acc[mt][nt][2], acc[mt][nt][3]);
        }
    }
}

// ============================================================================
// Fused zero + histogram. grid 128 = (16 px-chunks) x (8 b).
// Each block: partial histogram of its 1024 px -> atomicAdd to g_cnt,
// plus zeroes its 1/128 slice of g_sums.
// ============================================================================
__global__ void __launch_bounds__(256) zh_kernel(const int* __restrict__ label)
{
    __shared__ int hc[L];
    const int t = threadIdx.x;
    const int chunk = blockIdx.x & 15, b = blockIdx.x >> 4;

    // zero slice of g_sums: 83968 / 128 = 656
    {
        int base = blockIdx.x * 656;
        for (int i = t; i < 656; i += 256) g_sums[base + i] = 0.f;
    }

    if (t < L) hc[t] = 0;
    __syncthreads();
    for (int i = t; i < 1024; i += 256) {
        int p = chunk*1024 + i;
        int lb = label[(b*512 + ((p >> 7) << 2))*512 + ((p & 127) << 2)];
        atomicAdd(&hc[lb], 1);
    }
    __syncthreads();
    if (t < L) atomicAdd(&g_cnt[b*L + t], hc[t]);
}

// g_cnt must be zeroed before zh accumulates; tiny dedicated kernel (328 ints)
__global__ void cnt_zero_kernel()
{
    int i = blockIdx.x * blockDim.x + threadIdx.x;
    if (i < B*L) g_cnt[i] = 0;
}

// ============================================================================
// Segment sums as one-hot GEMM (fp16 m16n8k16), smem-free.  (R14 exact.)
// set=0: A from d (fp32 -> cvt). set=1: A direct u32 loads from half g_fuse.
// ============================================================================
__global__ void __launch_bounds__(256) stats_mma(const float* __restrict__ dd,
                                                 const int*   __restrict__ label)
{
    const int t = threadIdx.x, w = t >> 5, lane = t & 31;
    const int gid = lane >> 2, tid4 = lane & 3;
    const int kc = blockIdx.x, b = blockIdx.y, set = blockIdx.z;
    const float* Xf = dd + (size_t)b * 128 * 16384;
    const __half* Xh = g_fuse + (size_t)b * 128 * 16384;
    const int c0 = w * 16;

    float acc[6][4];
    #pragma unroll
    for (int i = 0; i < 6; i++)
        #pragma unroll
        for (int q = 0; q < 4; q++) acc[i][q] = 0.f;

    for (int chunk = 0; chunk < 32; chunk++) {
        const int p0 = kc*1024 + chunk*32;
        const int p = p0 + lane;
        const int ll = label[(b*512 + ((p >> 7) << 2))*512 + ((p & 127) << 2)];

        #pragma unroll
        for (int ks = 0; ks < 2; ks++) {
            const int koff = ks*16 + 2*tid4;
            uint32_t a0, a1, a2, a3;
            if (set == 0) {
                const float* xr = Xf + (size_t)(c0 + gid)*16384 + p0 + koff;
                float2 f0 = *(const float2*)(xr);
                float2 f1 = *(const float2*)(xr + (size_t)8*16384);
                float2 f2 = *(const float2*)(xr + 8);
                float2 f3 = *(const float2*)(xr + (size_t)8*16384 + 8);
                a0 = h2_u32(__floats2half2_rn(f0.x, f0.y));
                a1 = h2_u32(__floats2half2_rn(f1.x, f1.y));
                a2 = h2_u32(__floats2half2_rn(f2.x, f2.y));
                a3 = h2_u32(__floats2half2_rn(f3.x, f3.y));
            } else {
                const __half* xr = Xh + (size_t)(c0 + gid)*16384 + p0 + koff;
                a0 = *(const uint32_t*)(xr);
                a1 = *(const uint32_t*)(xr + (size_t)8*16384);
                a2 = *(const uint32_t*)(xr + 8);
                a3 = *(const uint32_t*)(xr + (size_t)8*16384 + 8);
            }

            int l0 = __shfl_sync(0xffffffffu, ll, koff);
            int l1 = __shfl_sync(0xffffffffu, ll, koff + 1);
            int l2 = __shfl_sync(0xffffffffu, ll, koff + 8);
            int l3 = __shfl_sync(0xffffffffu, ll, koff + 9);

            #pragma unroll
            for (int nt = 0; nt < 6; nt++) {
                int cls = nt*8 + gid;
                uint32_t b0 = ((l0 == cls) ? 0x3C00u : 0u) | ((l1 == cls) ? 0x3C000000u : 0u);
                uint32_t b1 = ((l2 == cls) ? 0x3C00u : 0u) | ((l3 == cls) ? 0x3C000000u : 0u);
                mma_f16(acc[nt], a0, a1, a2, a3, b0, b1);
            }
        }
    }

    float* gs = g_sums + (size_t)(set*B + b) * L * C;
    int c = c0 + gid;
    #pragma unroll
    for (int nt = 0; nt < 6; nt++) {
        int l0 = nt*8 + 2*tid4;
        if (l0 < L)     atomicAdd(&gs[l0*128 + c],        acc[nt][0]);
        if (l0 + 1 < L) atomicAdd(&gs[(l0+1)*128 + c],    acc[nt][1]);
        if (l0 < L)     atomicAdd(&gs[l0*128 + c + 8],    acc[nt][2]);
        if (l0 + 1 < L) atomicAdd(&gs[(l0+1)*128 + c + 8], acc[nt][3]);
    }
}

// ============================================================================
__global__ void __launch_bounds__(128) gate_kernel(const float* __restrict__ fw1,
                                                   const float* __restrict__ fw2,
                                                   const float* __restrict__ dw1,
                                                   const float* __restrict__ dw2,
                                                   const float* __restrict__ basef,
                                                   const float* __restrict__ based)
{
    __shared__ float ss[128];
    __shared__ float sh[8];
    const int c = threadIdx.x;
    const int b = blockIdx.x, set = blockIdx.y;
    const float* sums = g_sums + (set*B + b)*L*C;
    const float* base = ((set == 0) ? based : basef) + b*L*C;
    const int*   cnt  = g_cnt + b*L;

    float suml = 0.f, sq = 0.f;
    for (int l = 0; l < L; l++) {
        int n = cnt[l];
        float m = (n > 0) ? sums[l*128 + c] / (float)n : base[l*128 + c];
        suml += m; sq += m*m;
    }
    ss[c] = suml / fmaxf(sqrtf(sq), 1e-12f);
    __syncthreads();

    if (c < 8) {
        const float* w1 = ((set == 0) ? dw1 : fw1) + c*128;
        float hsum = 0.f;
        for (int k = 0; k < 128; k++) hsum += ss[k] * w1[k];
        sh[c] = fmaxf(hsum, 0.f);
    }
    __syncthreads();

    const float* w2 = ((set == 0) ? dw2 : fw2) + c*8;
    float g = 0.f;
    #pragma unroll
    for (int o = 0; o < 8; o++) g += sh[o] * w2[o];
    g_gates[(set*B + b)*C + c] = 1.f / (1.f + expf(-g));
}

// ============================================================================
// out = fuse(half) * gate_f[b,c] + d * gate_d[b,c]
// ============================================================================
__global__ void __launch_bounds__(256) out_kernel(const float* __restrict__ dd,
                                                  float* __restrict__ out)
{
    int idx = blockIdx.x * blockDim.x + threadIdx.x;   // float4 index
    int bc = idx >> 12;
    int b = bc >> 7, c = bc & 127;
    float gf = g_gates[(B + b)*C + c];
    float gd = g_gates[b*C + c];
    uint2 fh = ((const uint2*)g_fuse)[idx];
    float2 fa = __half22float2(*(__half2*)&fh.x);
    float2 fb = __half22float2(*(__half2*)&fh.y);
    float4 d4 = ((const float4*)dd)[idx];
    float4 o;
    o.x = fa.x*gf + d4.x*gd;
    o.y = fa.y*gf + d4.y*gd;
    o.z = fb.x*gf + d4.z*gd;
    o.w = fb.y*gf + d4.w*gd;
    ((float4*)out)[idx] = o;
}

// ============================================================================
extern "C" void kernel_launch(void* const* d_in, const int* in_sizes, int n_in,
                              void* d_out, int out_size)
{
    const float* r   = (const float*)d_in[0];
    const float* d   = (const float*)d_in[1];
    const int*   lab = (const int*)  d_in[2];
    const float* cw  = (const float*)d_in[3];
    const float* fw1 = (const float*)d_in[4];
    const float* fw2 = (const float*)d_in[5];
    const float* dw1 = (const float*)d_in[6];
    const float* dw2 = (const float*)d_in[7];
    const float* bf  = (const float*)d_in[8];
    const float* bd  = (const float*)d_in[9];
    float* out = (float*)d_out;

    static int inited = 0;
    if (!inited) {
        cudaFuncSetAttribute(conv_mma, cudaFuncAttributeMaxDynamicSharedMemorySize, CONV_SMEM);
        inited = 1;
    }

    __half* vin_ptr = nullptr;
    __half* wH_ptr = nullptr;
    cudaGetSymbolAddress((void**)&vin_ptr, g_vin);
    cudaGetSymbolAddress((void**)&wH_ptr,  g_wH);

    prep_kernel<<<1168, 256>>>(r, d, cw);              // vin + wpre fused
    cnt_zero_kernel<<<2, 256>>>();
    zh_kernel<<<128, 256>>>(lab);                      // zero sums + histogram
    conv_mma<<<dim3(64, 2, 8), 256, CONV_SMEM>>>(vin_ptr, wH_ptr);
    stats_mma<<<dim3(16, 8, 2), 256>>>(d, lab);
    gate_kernel<<<dim3(8, 2), 128>>>(fw1, fw2, dw1, dw2, bf, bd);
    out_kernel<<<16384, 256>>>(d, out);
}